// round 13
// baseline (speedup 1.0000x reference)
#include <cuda_runtime.h>
#include <cstdint>

#define RES   64
#define CH    8
#define NB    64
#define CORE  32
#define POS   16
#define DIMSZ (CORE*CORE*CORE*CH)   // 262144
#define BATCH 32

// ---- GEMM geometry: D=8 dims x B=8 batches per thread ----
#define DPB   512                          // dims per gemm block
#define CBLK  (DIMSZ / DPB)                // 512 gemm blocks
#define SMEM_U_BYTES (DPB * NB * 4)        // 128 KB U tile
#define SMEM_Z_BYTES (NB * BATCH * 8)      // 16 KB packed zL
#define SMEM_TOTAL   (SMEM_U_BYTES + SMEM_Z_BYTES)   // 144 KB

// ---- zero geometry (R10-proven: 34.7us @ 5.4TB/s) ----
#define F4_TOTAL  (BATCH*CH*RES*RES*RES/4) // 16,777,216 float4
#define F4_PER_TH 8
#define ZBLK (F4_TOTAL / (256 * F4_PER_TH))  // 8192

#define FMA2(a, u, s) asm("fma.rn.f32x2 %0, %1, %2, %0;" : "+l"(a) : "l"(u), "l"(s))

// ---------------------------------------------------------------------------
// Kernel 1: periphery zero-fill. 16 regs, 0 smem -> co-resides with the fat
// GEMM CTA on the same SM (this is what R12's fused version destroyed).
// ---------------------------------------------------------------------------
__global__ void __launch_bounds__(256, 8) zero_periphery(float* __restrict__ out)
{
    const int tid = threadIdx.x;
    const int zb  = blockIdx.x;
    const float4 zero4 = make_float4(0.f, 0.f, 0.f, 0.f);
    float4* o4 = reinterpret_cast<float4*>(out);
#pragma unroll
    for (int c = 0; c < F4_PER_TH; c++) {
        const int f = zb * (256 * F4_PER_TH) + c * 256 + tid;
        const unsigned w4 = f & 15;
        const unsigned j  = (f >> 4)  & 63;
        const unsigned i  = (f >> 10) & 63;
        const bool in_core = (i - 16u < 32u) & (j - 16u < 32u) & (w4 - 4u < 8u);
        if (!in_core) __stcs(&o4[f], zero4);   // core written by GEMM kernel
    }
}

// ---------------------------------------------------------------------------
// Kernel 2: smem-tiled GEMM, 8 dims x 8 batches per thread.
// LDS bytes per FFMA2: 3 (vs 5 before), zL part is warp-broadcast (~free).
// U tile stored as two 16B-stride planes: su[k][half][q][4 floats] so each of
// the thread's two LDS.128 (half=0,1) is lane-contiguous -> conflict-free.
// ---------------------------------------------------------------------------
__global__ void __launch_bounds__(256, 1) core_gemm(
    const float* __restrict__ z,   // (32, 64)
    const float* __restrict__ U,   // (64, 262144)
    const float* __restrict__ L,   // (64,)
    const float* __restrict__ mu,  // (262144,)
    float* __restrict__ out)       // (32, 8, 64, 64, 64)
{
    extern __shared__ char smem[];
    float* su = reinterpret_cast<float*>(smem);                      // [NB][2][64][4]
    unsigned long long* szb =
        reinterpret_cast<unsigned long long*>(smem + SMEM_U_BYTES);  // [NB][BATCH]

    const int tid = threadIdx.x;
    const int D0  = blockIdx.x * DPB;

    // zL packed duplicated-f32x2, layout [k][batch].
    for (int idx = tid; idx < NB * BATCH; idx += 256) {
        const int b = idx & 31;
        const int k = idx >> 5;
        float v = L[k] * z[b * NB + k];
        unsigned int vb = __float_as_uint(v);
        unsigned long long p;
        asm("mov.b64 %0, {%1, %1};" : "=l"(p) : "r"(vb));
        szb[k * BATCH + b] = p;
    }

    // Stage U tile: 64 k-rows x 512 floats = 8192 float4, 32 per thread.
    // gmem perfectly coalesced; STS has a benign 2-way conflict (~4us total).
#pragma unroll
    for (int i = 0; i < 32; i++) {
        const int idx = i * 256 + tid;
        const int k   = idx >> 7;        // 0..63
        const int m   = idx & 127;       // float4 within row
        const float4 v = *reinterpret_cast<const float4*>(
            U + (size_t)k * DIMSZ + D0 + m * 4);
        const int half = m & 1, q = m >> 1;
        *reinterpret_cast<float4*>(&su[((k * 2 + half) * 64 + q) * 4]) = v;
    }
    __syncthreads();

    const int g  = tid >> 6;         // batch group 0..3 (whole warps share g)
    const int q  = tid & 63;         // dim-octet 0..63
    const int b0 = g * 8;
    const int d0 = D0 + q * 8;       // 8 dims per thread

    const ulonglong2 mu_a = *reinterpret_cast<const ulonglong2*>(mu + d0);
    const ulonglong2 mu_b = *reinterpret_cast<const ulonglong2*>(mu + d0 + 4);

    unsigned long long acc[8][4];    // 8 batches x 8 dims = 32 u64 = 64 regs
#pragma unroll
    for (int bb = 0; bb < 8; bb++) {
        acc[bb][0] = mu_a.x; acc[bb][1] = mu_a.y;
        acc[bb][2] = mu_b.x; acc[bb][3] = mu_b.y;
    }

#pragma unroll 4
    for (int k = 0; k < NB; k++) {
        // Two conflict-free LDS.128: lane-contiguous within each half-plane.
        const ulonglong2 u0 = *reinterpret_cast<const ulonglong2*>(
            &su[((k * 2 + 0) * 64 + q) * 4]);            // dims d0..d0+3
        const ulonglong2 u1 = *reinterpret_cast<const ulonglong2*>(
            &su[((k * 2 + 1) * 64 + q) * 4]);            // dims d0+4..d0+7
        const ulonglong2* zp = reinterpret_cast<const ulonglong2*>(
            &szb[k * BATCH + b0]);
        const ulonglong2 z01 = zp[0];                    // broadcast LDS.128 x4
        const ulonglong2 z23 = zp[1];
        const ulonglong2 z45 = zp[2];
        const ulonglong2 z67 = zp[3];

        FMA2(acc[0][0], u0.x, z01.x); FMA2(acc[0][1], u0.y, z01.x);
        FMA2(acc[0][2], u1.x, z01.x); FMA2(acc[0][3], u1.y, z01.x);
        FMA2(acc[1][0], u0.x, z01.y); FMA2(acc[1][1], u0.y, z01.y);
        FMA2(acc[1][2], u1.x, z01.y); FMA2(acc[1][3], u1.y, z01.y);
        FMA2(acc[2][0], u0.x, z23.x); FMA2(acc[2][1], u0.y, z23.x);
        FMA2(acc[2][2], u1.x, z23.x); FMA2(acc[2][3], u1.y, z23.x);
        FMA2(acc[3][0], u0.x, z23.y); FMA2(acc[3][1], u0.y, z23.y);
        FMA2(acc[3][2], u1.x, z23.y); FMA2(acc[3][3], u1.y, z23.y);
        FMA2(acc[4][0], u0.x, z45.x); FMA2(acc[4][1], u0.y, z45.x);
        FMA2(acc[4][2], u1.x, z45.x); FMA2(acc[4][3], u1.y, z45.x);
        FMA2(acc[5][0], u0.x, z45.y); FMA2(acc[5][1], u0.y, z45.y);
        FMA2(acc[5][2], u1.x, z45.y); FMA2(acc[5][3], u1.y, z45.y);
        FMA2(acc[6][0], u0.x, z67.x); FMA2(acc[6][1], u0.y, z67.x);
        FMA2(acc[6][2], u1.x, z67.x); FMA2(acc[6][3], u1.y, z67.x);
        FMA2(acc[7][0], u0.x, z67.y); FMA2(acc[7][1], u0.y, z67.y);
        FMA2(acc[7][2], u1.x, z67.y); FMA2(acc[7][3], u1.y, z67.y);
    }

    // Scatter this thread's 8-dim chunk for its 8 batches into the core.
    // w = d0 & 31 in {0,8,16,24} -> both float4 stores 16B aligned.
    const int w = d0 & 31;
    const int j = (d0 >> 5) & 31;
    const int i = (d0 >> 10) & 31;
    const int c = d0 >> 15;

    const size_t obase = (size_t)c * (RES * RES * RES)
                       + (size_t)(i + POS) * (RES * RES)
                       + (size_t)(j + POS) * RES
                       + (size_t)(w + POS);

#pragma unroll
    for (int bb = 0; bb < 8; bb++) {
        float* o = out + (size_t)(b0 + bb) * (CH * RES * RES * RES) + obase;
        float4 v0, v1;
        v0.x = __uint_as_float((unsigned)(acc[bb][0]));
        v0.y = __uint_as_float((unsigned)(acc[bb][0] >> 32));
        v0.z = __uint_as_float((unsigned)(acc[bb][1]));
        v0.w = __uint_as_float((unsigned)(acc[bb][1] >> 32));
        v1.x = __uint_as_float((unsigned)(acc[bb][2]));
        v1.y = __uint_as_float((unsigned)(acc[bb][2] >> 32));
        v1.z = __uint_as_float((unsigned)(acc[bb][3]));
        v1.w = __uint_as_float((unsigned)(acc[bb][3] >> 32));
        __stcs(reinterpret_cast<float4*>(o),     v0);
        __stcs(reinterpret_cast<float4*>(o + 4), v1);
    }
}

// ---------------------------------------------------------------------------
// Launcher: fork-join stream capture -> two PARALLEL graph nodes.
// ---------------------------------------------------------------------------
static cudaStream_t g_s2 = nullptr;
static cudaEvent_t  g_evFork = nullptr, g_evJoin = nullptr;

extern "C" void kernel_launch(void* const* d_in, const int* in_sizes, int n_in,
                              void* d_out, int out_size)
{
    const float* z  = (const float*)d_in[0];
    const float* U  = (const float*)d_in[1];
    const float* L  = (const float*)d_in[2];
    const float* mu = (const float*)d_in[3];
    float* out = (float*)d_out;

    if (g_s2 == nullptr) {
        cudaStreamCreateWithFlags(&g_s2, cudaStreamNonBlocking);
        cudaEventCreateWithFlags(&g_evFork, cudaEventDisableTiming);
        cudaEventCreateWithFlags(&g_evJoin, cudaEventDisableTiming);
        cudaFuncSetAttribute(core_gemm,
                             cudaFuncAttributeMaxDynamicSharedMemorySize,
                             SMEM_TOTAL);
    }

    // Fork: second stream joins the capture as a parallel branch.
    cudaEventRecord(g_evFork, 0);
    cudaStreamWaitEvent(g_s2, g_evFork, 0);

    core_gemm<<<CBLK, 256, SMEM_TOTAL, g_s2>>>(z, U, L, mu, out);  // branch
    zero_periphery<<<ZBLK, 256, 0, 0>>>(out);                      // capture stream

    // Join.
    cudaEventRecord(g_evJoin, g_s2);
    cudaStreamWaitEvent(0, g_evJoin, 0);
}

// round 14
// speedup vs baseline: 1.0478x; 1.0478x over previous
#include <cuda_runtime.h>
#include <cstdint>

#define RES   64
#define CH    8
#define NB    64
#define CORE  32
#define POS   16
#define DIMSZ (CORE*CORE*CORE*CH)   // 262144
#define BATCH 32

// ---- GEMM geometry: small tile so zero blocks keep 4 CTAs/SM ----
#define DPB   128                          // dims per gemm block
#define CBLK  (DIMSZ / DPB)                // 2048 gemm blocks
#define SMEM_U_BYTES (DPB * NB * 4)        // 32 KB U tile
#define SMEM_Z_BYTES (NB * BATCH * 8)      // 16 KB packed zL
#define SMEM_TOTAL   (SMEM_U_BYTES + SMEM_Z_BYTES)   // 48 KB

// ---- zero geometry (proven 7.0 TB/s path) ----
#define F4_TOTAL  (BATCH*CH*RES*RES*RES/4) // 16,777,216 float4
#define F4_PER_TH 8
#define ZBLK (F4_TOTAL / (256 * F4_PER_TH))  // 8192 zero blocks

#define GRID (CBLK + ZBLK)                 // 10240 = 5 * 2048 -> 1:4 interleave

#define FMA2(a, u, s) asm("fma.rn.f32x2 %0, %1, %2, %0;" : "+l"(a) : "l"(u), "l"(s))

// One kernel, two block types interleaved 1 gemm : 4 zero in dispatch order.
// Both types fit 4 CTAs/SM (48KB smem, <=64 regs), so every SM carries a
// write-stream alongside GEMM work for the whole kernel duration.
__global__ void __launch_bounds__(256, 4) core_subspace_fused(
    const float* __restrict__ z,   // (32, 64)
    const float* __restrict__ U,   // (64, 262144)
    const float* __restrict__ L,   // (64,)
    const float* __restrict__ mu,  // (262144,)
    float* __restrict__ out)       // (32, 8, 64, 64, 64)
{
    extern __shared__ char smem[];
    const int tid = threadIdx.x;
    const int bid = blockIdx.x;
    const int g5  = bid / 5;
    const int r5  = bid - g5 * 5;

    if (r5 != 0) {
        // ---------------- periphery zero-fill (proven path) ----------------
        const int zb = g5 * 4 + (r5 - 1);            // 0..8191
        const float4 zero4 = make_float4(0.f, 0.f, 0.f, 0.f);
        float4* o4 = reinterpret_cast<float4*>(out);
#pragma unroll
        for (int c = 0; c < F4_PER_TH; c++) {
            const int f = zb * (256 * F4_PER_TH) + c * 256 + tid;
            const unsigned w4 = f & 15;
            const unsigned j  = (f >> 4)  & 63;
            const unsigned i  = (f >> 10) & 63;
            const bool in_core = (i - 16u < 32u) & (j - 16u < 32u) & (w4 - 4u < 8u);
            if (!in_core) __stcs(&o4[f], zero4);     // core written by gemm blocks
        }
        return;
    }

    // ---------------- small-tile GEMM: 4 dims x 4 batches per thread -------
    float* su = reinterpret_cast<float*>(smem);                      // [NB][DPB]
    unsigned long long* szb =
        reinterpret_cast<unsigned long long*>(smem + SMEM_U_BYTES);  // [NB][BATCH]

    const int D0 = g5 * DPB;                          // gemm block id = g5

    // zL packed duplicated-f32x2, layout [k][batch].
    for (int idx = tid; idx < NB * BATCH; idx += 256) {
        const int b = idx & 31;
        const int k = idx >> 5;
        float v = L[k] * z[b * NB + k];
        unsigned int vb = __float_as_uint(v);
        unsigned long long p;
        asm("mov.b64 %0, {%1, %1};" : "=l"(p) : "r"(vb));
        szb[k * BATCH + b] = p;
    }

    // Stage U tile: 64 rows x 128 floats = 2048 float4, 8 per thread.
#pragma unroll
    for (int i = 0; i < 8; i++) {
        const int idx = i * 256 + tid;
        const int k   = idx >> 5;        // 0..63
        const int c4  = idx & 31;        // float4 within row
        const float4 v = *reinterpret_cast<const float4*>(
            U + (size_t)k * DIMSZ + D0 + c4 * 4);
        *reinterpret_cast<float4*>(&su[k * DPB + c4 * 4]) = v;
    }
    __syncthreads();

    const int g  = tid >> 5;         // batch group 0..7 (4 batches each)
    const int q  = tid & 31;         // dim-quad 0..31
    const int b0 = g * 4;
    const int d0 = D0 + q * 4;

    const ulonglong2 mu2 = *reinterpret_cast<const ulonglong2*>(mu + d0);

    unsigned long long acc[4][2];    // 16 registers
#pragma unroll
    for (int bb = 0; bb < 4; bb++) { acc[bb][0] = mu2.x; acc[bb][1] = mu2.y; }

#pragma unroll 8
    for (int k = 0; k < NB; k++) {
        const ulonglong2 ud = *reinterpret_cast<const ulonglong2*>(
            &su[k * DPB + q * 4]);                       // LDS.128, conflict-free
        const ulonglong2* zp = reinterpret_cast<const ulonglong2*>(
            &szb[k * BATCH + b0]);
        const ulonglong2 z01 = zp[0];                    // LDS.128 broadcast x2
        const ulonglong2 z23 = zp[1];

        FMA2(acc[0][0], ud.x, z01.x); FMA2(acc[0][1], ud.y, z01.x);
        FMA2(acc[1][0], ud.x, z01.y); FMA2(acc[1][1], ud.y, z01.y);
        FMA2(acc[2][0], ud.x, z23.x); FMA2(acc[2][1], ud.y, z23.x);
        FMA2(acc[3][0], ud.x, z23.y); FMA2(acc[3][1], ud.y, z23.y);
    }

    // Scatter 4-dim chunk into the core for this thread's 4 batches.
    // dim = ((c*32 + i)*32 + j)*32 + w ; w multiple of 4 -> 16B aligned.
    const int w = d0 & 31;
    const int j = (d0 >> 5) & 31;
    const int i = (d0 >> 10) & 31;
    const int c = d0 >> 15;

    const size_t obase = (size_t)c * (RES * RES * RES)
                       + (size_t)(i + POS) * (RES * RES)
                       + (size_t)(j + POS) * RES
                       + (size_t)(w + POS);

#pragma unroll
    for (int bb = 0; bb < 4; bb++) {
        float* o = out + (size_t)(b0 + bb) * (CH * RES * RES * RES) + obase;
        float4 v;
        v.x = __uint_as_float((unsigned)(acc[bb][0]));
        v.y = __uint_as_float((unsigned)(acc[bb][0] >> 32));
        v.z = __uint_as_float((unsigned)(acc[bb][1]));
        v.w = __uint_as_float((unsigned)(acc[bb][1] >> 32));
        __stcs(reinterpret_cast<float4*>(o), v);
    }
}

extern "C" void kernel_launch(void* const* d_in, const int* in_sizes, int n_in,
                              void* d_out, int out_size)
{
    const float* z  = (const float*)d_in[0];
    const float* U  = (const float*)d_in[1];
    const float* L  = (const float*)d_in[2];
    const float* mu = (const float*)d_in[3];
    float* out = (float*)d_out;

    static bool attr_set = false;
    if (!attr_set) {
        cudaFuncSetAttribute(core_subspace_fused,
                             cudaFuncAttributeMaxDynamicSharedMemorySize,
                             SMEM_TOTAL);
        attr_set = true;
    }

    core_subspace_fused<<<GRID, 256, SMEM_TOTAL>>>(z, U, L, mu, out);
}